// round 1
// baseline (speedup 1.0000x reference)
#include <cuda_runtime.h>
#include <math.h>

// Problem constants (fixed by the reference)
#define B_  4
#define C_  64
#define O_  64
#define H_  128
#define W_  128
#define K2_ 9
#define HW_ (H_*W_)
#define CK_ (C_*K2_)          // 576

// ---------------- scratch (no allocations allowed) ----------------
__device__ float g_wom_t[CK_*28];          // transposed offset-conv weight, padded 27->28
__device__ float g_w_t  [CK_*O_];          // transposed main weight [ck][o]
__device__ float g_dy   [B_*K2_*HW_];
__device__ float g_dx   [B_*K2_*HW_];
__device__ float g_mask [B_*K2_*HW_];

// ---------------- packed f32x2 FMA (sm_100+) ----------------
__device__ __forceinline__ unsigned long long fma2(unsigned long long a,
                                                   unsigned long long b,
                                                   unsigned long long c) {
    unsigned long long d;
    asm("fma.rn.f32x2 %0, %1, %2, %3;" : "=l"(d) : "l"(a), "l"(b), "l"(c));
    return d;
}

// ---------------- kernel 0: weight transposes ----------------
__global__ void prep_weights(const float* __restrict__ w_om,
                             const float* __restrict__ weight) {
    int tid = blockIdx.x * blockDim.x + threadIdx.x;
    int stride = gridDim.x * blockDim.x;
    // w_om: [27][C][3][3] -> g_wom_t[ck][28] (pad zeroed)
    for (int i = tid; i < CK_*28; i += stride) {
        int ck = i / 28, r = i - ck*28;
        g_wom_t[i] = (r < 27) ? w_om[r*CK_ + ck] : 0.f;
    }
    // weight: [O][C][3][3] -> g_w_t[ck][O]
    for (int j = tid; j < CK_*O_; j += stride) {
        int ck = j >> 6, o = j & 63;
        g_w_t[j] = weight[o*CK_ + ck];
    }
}

// ---------------- kernel 1: offset/mask conv (27ch, 3x3, pad 1) ----------------
// grid (8,8,4), block 256 (16x16 pixel tile). SMEM: x tile 64x18x18 + weights 576x28.
__global__ void __launch_bounds__(256)
offset_conv(const float* __restrict__ x, const float* __restrict__ b_om) {
    extern __shared__ float smem[];
    float* xs = smem;                 // 64*18*18 = 20736 floats
    float* wA = smem + 64*18*18;      // 576*28  = 16128 floats

    const int tid = threadIdx.x;
    const int bx = blockIdx.x, by = blockIdx.y, b = blockIdx.z;

    for (int i = tid; i < CK_*28; i += 256) wA[i] = g_wom_t[i];

    const int gy0 = by*16 - 1, gx0 = bx*16 - 1;
    const float* xb = x + (size_t)b*C_*HW_;
    for (int i = tid; i < 64*18*18; i += 256) {
        int c = i / 324; int r = i - c*324;
        int sy = r / 18;  int sx = r - sy*18;
        int gy = gy0 + sy, gx = gx0 + sx;
        float v = 0.f;
        if (gy >= 0 && gy < H_ && gx >= 0 && gx < W_)
            v = xb[c*HW_ + gy*W_ + gx];
        xs[i] = v;
    }
    __syncthreads();

    const int ty = tid >> 4, tx = tid & 15;
    float acc[28];
    #pragma unroll
    for (int oc = 0; oc < 27; oc++) acc[oc] = b_om[oc];
    acc[27] = 0.f;

    for (int c = 0; c < C_; c++) {
        const float* xrow = xs + c*324 + ty*18 + tx;
        #pragma unroll
        for (int ky = 0; ky < 3; ky++) {
            #pragma unroll
            for (int kx = 0; kx < 3; kx++) {
                float v = xrow[ky*18 + kx];
                const float4* wr4 = (const float4*)(wA + (c*9 + ky*3 + kx)*28);
                #pragma unroll
                for (int q = 0; q < 7; q++) {
                    float4 w4 = wr4[q];
                    acc[4*q+0] = fmaf(v, w4.x, acc[4*q+0]);
                    acc[4*q+1] = fmaf(v, w4.y, acc[4*q+1]);
                    acc[4*q+2] = fmaf(v, w4.z, acc[4*q+2]);
                    acc[4*q+3] = fmaf(v, w4.w, acc[4*q+3]);
                }
            }
        }
    }

    const int y = by*16 + ty, xq = bx*16 + tx;
    const int pix = y*W_ + xq;
    #pragma unroll
    for (int k = 0; k < 9; k++) {
        int base = (b*9 + k)*HW_ + pix;
        g_dy[base]   = acc[2*k];
        g_dx[base]   = acc[2*k + 1];
        g_mask[base] = 1.f / (1.f + __expf(-acc[18 + k]));
    }
}

// ---------------- kernel 2: fused bilinear sample + output GEMM ----------------
// grid 256, block 256: one output pixel per thread, 64 output channels packed
// as 32 x f32x2 accumulators. Full transposed weight (576x64) in SMEM.
__global__ void __launch_bounds__(256)
deform_out(const float* __restrict__ x, const float* __restrict__ bias,
           float* __restrict__ out) {
    extern __shared__ float sw[];     // 576*64 floats = 147456 B
    {
        const float4* src = (const float4*)g_w_t;
        float4* dst = (float4*)sw;
        for (int i = threadIdx.x; i < CK_*O_/4; i += 256) dst[i] = src[i];
    }
    __syncthreads();

    const int p   = blockIdx.x*256 + threadIdx.x;   // 0..65535
    const int b   = p >> 14;
    const int pix = p & (HW_ - 1);
    const int y   = pix >> 7, xq = pix & 127;
    const float* xb = x + (size_t)b*C_*HW_;

    unsigned long long acc[32];
    #pragma unroll
    for (int i = 0; i < 32; i++) acc[i] = 0ull;

    #pragma unroll 1
    for (int k = 0; k < 9; k++) {
        const int base = (b*9 + k)*HW_ + pix;
        const float m  = g_mask[base];
        const int ky = k / 3, kx = k - ky*3;
        const float sy = g_dy[base] + (float)(ky + y - 1);
        const float sx = g_dx[base] + (float)(kx + xq - 1);

        const float y0f = floorf(sy), x0f = floorf(sx);
        const int iy0 = (int)y0f, ix0 = (int)x0f;
        const float wy1 = sy - y0f, wx1 = sx - x0f;
        const float wy0 = 1.f - wy1, wx0 = 1.f - wx1;

        const bool vy0 = (iy0   >= 0) && (iy0   < H_);
        const bool vy1 = (iy0+1 >= 0) && (iy0+1 < H_);
        const bool vx0 = (ix0   >= 0) && (ix0   < W_);
        const bool vx1 = (ix0+1 >= 0) && (ix0+1 < W_);

        const int y0c = min(max(iy0,   0), H_-1);
        const int y1c = min(max(iy0+1, 0), H_-1);
        const int x0c = min(max(ix0,   0), W_-1);
        const int x1c = min(max(ix0+1, 0), W_-1);

        const int o00 = y0c*W_ + x0c, o01 = y0c*W_ + x1c;
        const int o10 = y1c*W_ + x0c, o11 = y1c*W_ + x1c;

        // fold mask + validity into bilinear coefficients
        const float c00 = (vy0 && vx0) ? wy0*wx0*m : 0.f;
        const float c01 = (vy0 && vx1) ? wy0*wx1*m : 0.f;
        const float c10 = (vy1 && vx0) ? wy1*wx0*m : 0.f;
        const float c11 = (vy1 && vx1) ? wy1*wx1*m : 0.f;

        const float* swk = sw + k*64;
        for (int c = 0; c < C_; c++) {
            const float* xp = xb + c*HW_;
            float v = c00 * xp[o00];
            v = fmaf(c01, xp[o01], v);
            v = fmaf(c10, xp[o10], v);
            v = fmaf(c11, xp[o11], v);

            unsigned long long vv;
            asm("mov.b64 %0, {%1, %1};" : "=l"(vv) : "f"(v));

            const ulonglong2* wr = (const ulonglong2*)(swk + c*(9*64));
            #pragma unroll
            for (int j = 0; j < 16; j++) {
                ulonglong2 w4 = wr[j];
                acc[2*j]   = fma2(vv, w4.x, acc[2*j]);
                acc[2*j+1] = fma2(vv, w4.y, acc[2*j+1]);
            }
        }
    }

    float* ob = out + (size_t)b*O_*HW_ + pix;
    #pragma unroll
    for (int i = 0; i < 32; i++) {
        float lo = __uint_as_float((unsigned)(acc[i] & 0xffffffffULL));
        float hi = __uint_as_float((unsigned)(acc[i] >> 32));
        ob[(size_t)(2*i  )*HW_] = lo + bias[2*i];
        ob[(size_t)(2*i+1)*HW_] = hi + bias[2*i+1];
    }
}

// ---------------- launch ----------------
extern "C" void kernel_launch(void* const* d_in, const int* in_sizes, int n_in,
                              void* d_out, int out_size) {
    const float* x      = (const float*)d_in[0];
    const float* w_om   = (const float*)d_in[1];
    const float* b_om   = (const float*)d_in[2];
    const float* weight = (const float*)d_in[3];
    const float* bias   = (const float*)d_in[4];
    float* out = (float*)d_out;

    const int SMEM_A = (64*18*18 + CK_*28) * 4;   // 147456
    const int SMEM_B = (CK_*O_) * 4;              // 147456
    cudaFuncSetAttribute(offset_conv, cudaFuncAttributeMaxDynamicSharedMemorySize, SMEM_A);
    cudaFuncSetAttribute(deform_out,  cudaFuncAttributeMaxDynamicSharedMemorySize, SMEM_B);

    prep_weights<<<64, 256>>>(w_om, weight);
    offset_conv<<<dim3(8, 8, B_), 256, SMEM_A>>>(x, b_om);
    deform_out<<<256, 256, SMEM_B>>>(x, bias, out);
}

// round 2
// speedup vs baseline: 1.1811x; 1.1811x over previous
#include <cuda_runtime.h>
#include <math.h>

// Problem constants (fixed by the reference)
#define B_  4
#define C_  64
#define O_  64
#define H_  128
#define W_  128
#define K2_ 9
#define HW_ (H_*W_)
#define CK_ (C_*K2_)          // 576

// ---------------- scratch (no allocations allowed) ----------------
__device__ float g_wom_t[CK_*28];          // transposed offset-conv weight, padded 27->28
__device__ float g_w_t  [CK_*O_];          // transposed main weight [ck][o]
__device__ float g_dy   [B_*K2_*HW_];
__device__ float g_dx   [B_*K2_*HW_];
__device__ float g_mask [B_*K2_*HW_];

// ---------------- packed f32x2 FMA (sm_100+) ----------------
__device__ __forceinline__ unsigned long long fma2(unsigned long long a,
                                                   unsigned long long b,
                                                   unsigned long long c) {
    unsigned long long d;
    asm("fma.rn.f32x2 %0, %1, %2, %3;" : "=l"(d) : "l"(a), "l"(b), "l"(c));
    return d;
}
__device__ __forceinline__ unsigned long long splat2(float v) {
    unsigned long long d;
    asm("mov.b64 %0, {%1, %1};" : "=l"(d) : "f"(v));
    return d;
}

// ---------------- kernel 0: weight transposes ----------------
__global__ void prep_weights(const float* __restrict__ w_om,
                             const float* __restrict__ weight) {
    int tid = blockIdx.x * blockDim.x + threadIdx.x;
    int stride = gridDim.x * blockDim.x;
    // w_om: [27][C][3][3] -> g_wom_t[ck][28] (pad zeroed)
    for (int i = tid; i < CK_*28; i += stride) {
        int ck = i / 28, r = i - ck*28;
        g_wom_t[i] = (r < 27) ? w_om[r*CK_ + ck] : 0.f;
    }
    // weight: [O][C][3][3] -> g_w_t[ck][O]
    for (int j = tid; j < CK_*O_; j += stride) {
        int ck = j >> 6, o = j & 63;
        g_w_t[j] = weight[o*CK_ + ck];
    }
}

// ---------------- kernel 1: offset/mask conv (27ch, 3x3, pad 1) ----------------
// 512 threads, grid 128 (one pixel per thread). No x tile: x reads go through
// L1/L2 (x is L2-resident, warp rows are coalesced). Weights in SMEM (64.5KB)
// -> plenty of occupancy headroom. Accumulators packed as f32x2 (14 pairs).
__global__ void __launch_bounds__(512)
offset_conv(const float* __restrict__ x, const float* __restrict__ b_om) {
    extern __shared__ float wA[];     // 576*28 floats = 64512 B

    const int tid = threadIdx.x;
    for (int i = tid; i < CK_*28; i += 512) wA[i] = g_wom_t[i];
    __syncthreads();

    const int p   = blockIdx.x*512 + tid;     // 0..65535
    const int b   = p >> 14;
    const int pix = p & (HW_ - 1);
    const int y   = pix >> 7, xq = pix & 127;
    const float* xb = x + (size_t)b*C_*HW_;

    const bool vy0 = (y  > 0),  vy2 = (y  < H_-1);
    const bool vx0 = (xq > 0),  vx2 = (xq < W_-1);
    const int base00 = (y-1)*W_ + (xq-1);

    unsigned long long acc[14];
    #pragma unroll
    for (int j = 0; j < 14; j++) acc[j] = 0ull;

    for (int c = 0; c < C_; c++) {
        const float* xp = xb + c*HW_ + base00;
        float v[9];
        v[0] = (vy0 && vx0) ? xp[0]        : 0.f;
        v[1] =  vy0         ? xp[1]        : 0.f;
        v[2] = (vy0 && vx2) ? xp[2]        : 0.f;
        v[3] =  vx0         ? xp[W_]       : 0.f;
        v[4] =                xp[W_+1];
        v[5] =  vx2         ? xp[W_+2]     : 0.f;
        v[6] = (vy2 && vx0) ? xp[2*W_]     : 0.f;
        v[7] =  vy2         ? xp[2*W_+1]   : 0.f;
        v[8] = (vy2 && vx2) ? xp[2*W_+2]   : 0.f;

        const float* wc = wA + c*9*28;
        #pragma unroll
        for (int t = 0; t < 9; t++) {
            unsigned long long vv = splat2(v[t]);
            const ulonglong2* wr = (const ulonglong2*)(wc + t*28);
            #pragma unroll
            for (int q = 0; q < 7; q++) {
                ulonglong2 w4 = wr[q];
                acc[2*q]   = fma2(vv, w4.x, acc[2*q]);
                acc[2*q+1] = fma2(vv, w4.y, acc[2*q+1]);
            }
        }
    }

    // unpack: pair j<9 = {dy_j, dx_j}; pairs 9..13 = mask channels 18..26
    float a[28];
    #pragma unroll
    for (int j = 0; j < 14; j++) {
        a[2*j]   = __uint_as_float((unsigned)(acc[j] & 0xffffffffULL));
        a[2*j+1] = __uint_as_float((unsigned)(acc[j] >> 32));
    }
    #pragma unroll
    for (int k = 0; k < 9; k++) {
        int base = (b*9 + k)*HW_ + pix;
        g_dy[base]   = a[2*k]     + b_om[2*k];
        g_dx[base]   = a[2*k + 1] + b_om[2*k + 1];
        float mlog   = a[18 + k]  + b_om[18 + k];
        g_mask[base] = 1.f / (1.f + __expf(-mlog));
    }
}

// ---------------- kernel 2: fused bilinear sample + output GEMM ----------------
// 512 threads, grid 128 (one clean wave, 16 warps/SM). One output pixel per
// thread, 64 output channels packed as 32 x f32x2 accumulators. Full
// transposed weight (576x64) in SMEM.
__global__ void __launch_bounds__(512)
deform_out(const float* __restrict__ x, const float* __restrict__ bias,
           float* __restrict__ out) {
    extern __shared__ float sw[];     // 576*64 floats = 147456 B
    {
        const float4* src = (const float4*)g_w_t;
        float4* dst = (float4*)sw;
        for (int i = threadIdx.x; i < CK_*O_/4; i += 512) dst[i] = src[i];
    }
    __syncthreads();

    const int p   = blockIdx.x*512 + threadIdx.x;   // 0..65535
    const int b   = p >> 14;
    const int pix = p & (HW_ - 1);
    const int y   = pix >> 7, xq = pix & 127;
    const float* xb = x + (size_t)b*C_*HW_;

    unsigned long long acc[32];
    #pragma unroll
    for (int i = 0; i < 32; i++) acc[i] = 0ull;

    #pragma unroll 1
    for (int k = 0; k < 9; k++) {
        const int base = (b*9 + k)*HW_ + pix;
        const float m  = g_mask[base];
        const int ky = k / 3, kx = k - ky*3;
        const float sy = g_dy[base] + (float)(ky + y - 1);
        const float sx = g_dx[base] + (float)(kx + xq - 1);

        const float y0f = floorf(sy), x0f = floorf(sx);
        const int iy0 = (int)y0f, ix0 = (int)x0f;
        const float wy1 = sy - y0f, wx1 = sx - x0f;
        const float wy0 = 1.f - wy1, wx0 = 1.f - wx1;

        const bool vy0 = (iy0   >= 0) && (iy0   < H_);
        const bool vy1 = (iy0+1 >= 0) && (iy0+1 < H_);
        const bool vx0 = (ix0   >= 0) && (ix0   < W_);
        const bool vx1 = (ix0+1 >= 0) && (ix0+1 < W_);

        const int y0c = min(max(iy0,   0), H_-1);
        const int y1c = min(max(iy0+1, 0), H_-1);
        const int x0c = min(max(ix0,   0), W_-1);
        const int x1c = min(max(ix0+1, 0), W_-1);

        const int o00 = y0c*W_ + x0c, o01 = y0c*W_ + x1c;
        const int o10 = y1c*W_ + x0c, o11 = y1c*W_ + x1c;

        // fold mask + validity into bilinear coefficients
        const float c00 = (vy0 && vx0) ? wy0*wx0*m : 0.f;
        const float c01 = (vy0 && vx1) ? wy0*wx1*m : 0.f;
        const float c10 = (vy1 && vx0) ? wy1*wx0*m : 0.f;
        const float c11 = (vy1 && vx1) ? wy1*wx1*m : 0.f;

        const float* swk = sw + k*64;
        for (int c = 0; c < C_; c++) {
            const float* xp = xb + c*HW_;
            float v = c00 * xp[o00];
            v = fmaf(c01, xp[o01], v);
            v = fmaf(c10, xp[o10], v);
            v = fmaf(c11, xp[o11], v);

            unsigned long long vv = splat2(v);

            const ulonglong2* wr = (const ulonglong2*)(swk + c*(9*64));
            #pragma unroll
            for (int j = 0; j < 16; j++) {
                ulonglong2 w4 = wr[j];
                acc[2*j]   = fma2(vv, w4.x, acc[2*j]);
                acc[2*j+1] = fma2(vv, w4.y, acc[2*j+1]);
            }
        }
    }

    float* ob = out + (size_t)b*O_*HW_ + pix;
    #pragma unroll
    for (int i = 0; i < 32; i++) {
        float lo = __uint_as_float((unsigned)(acc[i] & 0xffffffffULL));
        float hi = __uint_as_float((unsigned)(acc[i] >> 32));
        ob[(size_t)(2*i  )*HW_] = lo + bias[2*i];
        ob[(size_t)(2*i+1)*HW_] = hi + bias[2*i+1];
    }
}

// ---------------- launch ----------------
extern "C" void kernel_launch(void* const* d_in, const int* in_sizes, int n_in,
                              void* d_out, int out_size) {
    const float* x      = (const float*)d_in[0];
    const float* w_om   = (const float*)d_in[1];
    const float* b_om   = (const float*)d_in[2];
    const float* weight = (const float*)d_in[3];
    const float* bias   = (const float*)d_in[4];
    float* out = (float*)d_out;

    const int SMEM_A = (CK_*28) * 4;              // 64512
    const int SMEM_B = (CK_*O_) * 4;              // 147456
    cudaFuncSetAttribute(offset_conv, cudaFuncAttributeMaxDynamicSharedMemorySize, SMEM_A);
    cudaFuncSetAttribute(deform_out,  cudaFuncAttributeMaxDynamicSharedMemorySize, SMEM_B);

    prep_weights<<<64, 256>>>(w_om, weight);
    offset_conv<<<128, 512, SMEM_A>>>(x, b_om);
    deform_out<<<128, 512, SMEM_B>>>(x, bias, out);
}